// round 4
// baseline (speedup 1.0000x reference)
#include <cuda_runtime.h>
#include <cuda_fp16.h>
#include <cuda_bf16.h>

// Problem constants: N=100000 nodes, D=512, E=6.4M edges, out_channels=1.
#define MAX_N 100000
#define NEG_SLOPE 0.2f

// Scratch (allocation-free rule: __device__ globals)
__device__ float  g_x[MAX_N];      // projected feature x = F @ W  [N] (fp32)
__device__ __half g_xh[MAX_N];     // fp16 copy for the smem gather table
__device__ float2 g_acc[MAX_N];    // per-dst {sum(w*x[src]), sum(w)}; zero-init, self-cleaned

// ---------------------------------------------------------------------------
// Kernel 1: x = F @ W.  Warp handles TWO rows (D=512: 128 float4/row) so 8
// independent LDG.128 are in flight per warp -> deeper MLP, higher DRAM util.
// ---------------------------------------------------------------------------
__global__ void __launch_bounds__(256) matvec_kernel(
    const float* __restrict__ F, const float* __restrict__ W, int n)
{
    __shared__ float4 sW[128];
    int tid = threadIdx.x;
    if (tid < 128) sW[tid] = reinterpret_cast<const float4*>(W)[tid];
    __syncthreads();

    int warp = tid >> 5;
    int lane = tid & 31;
    int r0   = (blockIdx.x * 8 + warp) * 2;       // 16 rows per block
    if (r0 >= n) return;
    bool has2 = (r0 + 1) < n;

    const float4* A0 = reinterpret_cast<const float4*>(F + (size_t)r0 * 512);
    const float4* A1 = A0 + 128;

    float s0 = 0.f, s1 = 0.f;
#pragma unroll
    for (int i = 0; i < 4; i++) {
        float4 a0 = A0[lane + 32 * i];
        float4 a1 = has2 ? A1[lane + 32 * i] : make_float4(0.f, 0.f, 0.f, 0.f);
        float4 b  = sW[lane + 32 * i];
        s0 += a0.x * b.x + a0.y * b.y + a0.z * b.z + a0.w * b.w;
        s1 += a1.x * b.x + a1.y * b.y + a1.z * b.z + a1.w * b.w;
    }
#pragma unroll
    for (int o = 16; o > 0; o >>= 1) {
        s0 += __shfl_xor_sync(0xffffffffu, s0, o);
        s1 += __shfl_xor_sync(0xffffffffu, s1, o);
    }

    if (lane == 0) {
        g_x[r0]  = s0;
        g_xh[r0] = __float2half(s0);
        if (has2) {
            g_x[r0 + 1]  = s1;
            g_xh[r0 + 1] = __float2half(s1);
        }
    }
}

// ---------------------------------------------------------------------------
// Kernel 2: persistent fused edge pass.
// x table staged in SMEM as fp16 (200 KB) -> gathers are LDS.
// Softmax max-subtraction dropped (exact ratio invariance; logits are O(1)).
// 8 edges per thread per iteration to amortize index loads + loop overhead;
// the RED.ADD.F32x2 scatter is the LSU-bound floor.
// ---------------------------------------------------------------------------
__device__ __forceinline__ void process_edge(
    const __half* __restrict__ sx, int s, int d, float as, float ad)
{
    float xs = __half2float(sx[s]);
    float xd = __half2float(sx[d]);
    float l  = fmaf(as, xs, ad * xd);
    l = (l > 0.f) ? l : NEG_SLOPE * l;
    float w = __expf(l);
    atomicAdd(&g_acc[d], make_float2(w * xs, w));
}

__global__ void __launch_bounds__(1024, 1) edge_kernel(
    const int* __restrict__ src, const int* __restrict__ dst,
    int e8, int etail_base, int etail_count, int n,
    const float* __restrict__ att_src, const float* __restrict__ att_dst)
{
    extern __shared__ __half sx[];

    // Stage x table: 100000 halves = 12500 uint4 (16B) vector loads from L2.
    {
        const uint4* xin = reinterpret_cast<const uint4*>(g_xh);
        uint4* xout = reinterpret_cast<uint4*>(sx);
        int nvec = n >> 3;                       // n % 8 == 0 for N=100000
        for (int i = threadIdx.x; i < nvec; i += blockDim.x)
            xout[i] = xin[i];
    }
    __syncthreads();

    const float as = __ldg(att_src);
    const float ad = __ldg(att_dst);

    int gid    = blockIdx.x * blockDim.x + threadIdx.x;
    int stride = gridDim.x * blockDim.x;

    const int4* src4 = reinterpret_cast<const int4*>(src);
    const int4* dst4 = reinterpret_cast<const int4*>(dst);

    for (int i = gid; i < e8; i += stride) {
        int4 s0 = __ldcs(src4 + 2 * i);
        int4 s1 = __ldcs(src4 + 2 * i + 1);
        int4 t0 = __ldcs(dst4 + 2 * i);
        int4 t1 = __ldcs(dst4 + 2 * i + 1);
        process_edge(sx, s0.x, t0.x, as, ad);
        process_edge(sx, s0.y, t0.y, as, ad);
        process_edge(sx, s0.z, t0.z, as, ad);
        process_edge(sx, s0.w, t0.w, as, ad);
        process_edge(sx, s1.x, t1.x, as, ad);
        process_edge(sx, s1.y, t1.y, as, ad);
        process_edge(sx, s1.z, t1.z, as, ad);
        process_edge(sx, s1.w, t1.w, as, ad);
    }
    // scalar tail (E not divisible by 8)
    if (gid < etail_count)
        process_edge(sx, src[etail_base + gid], dst[etail_base + gid], as, ad);
}

// ---------------------------------------------------------------------------
// Kernel 3: fold self-loop analytically, normalize, add bias, and SELF-CLEAN
// g_acc for the next graph replay (device globals are zero-init, so the
// first call is also correct).
// ---------------------------------------------------------------------------
__global__ void finalize_kernel(
    float* __restrict__ out, int n,
    const float* __restrict__ att_src, const float* __restrict__ att_dst,
    const float* __restrict__ bias)
{
    int i = blockIdx.x * blockDim.x + threadIdx.x;
    if (i >= n) return;
    float as = __ldg(att_src);
    float ad = __ldg(att_dst);
    float b  = __ldg(bias);

    float xi = g_x[i];
    float l  = (as + ad) * xi;
    l = (l > 0.f) ? l : NEG_SLOPE * l;
    float w = __expf(l);

    float2 a = g_acc[i];
    out[i] = __fdividef(a.x + w * xi, a.y + w) + b;
    g_acc[i] = make_float2(0.f, 0.f);           // clean for next replay
}

// ---------------------------------------------------------------------------
extern "C" void kernel_launch(void* const* d_in, const int* in_sizes, int n_in,
                              void* d_out, int out_size)
{
    const float* F       = (const float*)d_in[0];
    const int*   ei      = (const int*)  d_in[1];
    const float* W       = (const float*)d_in[2];
    const float* att_src = (const float*)d_in[3];
    const float* att_dst = (const float*)d_in[4];
    const float* bias    = (const float*)d_in[5];
    float*       out     = (float*)d_out;

    const int d = in_sizes[2];        // 512
    const int n = in_sizes[0] / d;    // 100000
    const int E = in_sizes[1] / 2;    // 6400000
    const int* src = ei;
    const int* dst = ei + E;

    const int smem_bytes = n * (int)sizeof(__half);     // 200000 B
    static int configured = 0;        // host-side config memo, not a work guard
    if (!configured) {
        cudaFuncSetAttribute(edge_kernel,
                             cudaFuncAttributeMaxDynamicSharedMemorySize,
                             smem_bytes);
        configured = 1;
    }
    int num_sms = 148;
    cudaDeviceGetAttribute(&num_sms, cudaDevAttrMultiProcessorCount, 0);

    // 1. projection (writes fp32 + fp16 x), 16 rows per block
    matvec_kernel<<<(n + 15) / 16, 256>>>(F, W, n);

    // 2. persistent fused edge pass, one 1024-thread block per SM
    int e8 = E / 8;
    int etail_base  = e8 * 8;
    int etail_count = E - etail_base;
    edge_kernel<<<num_sms, 1024, smem_bytes>>>(src, dst, e8, etail_base,
                                               etail_count, n, att_src, att_dst);

    // 3. self-loop fold + normalize + bias + accumulator clean
    finalize_kernel<<<(n + 255) / 256, 256>>>(out, n, att_src, att_dst, bias);
}

// round 5
// speedup vs baseline: 1.0247x; 1.0247x over previous
#include <cuda_runtime.h>
#include <cuda_fp16.h>
#include <cuda_bf16.h>

// Problem constants: N=100000 nodes, D=512, E=6.4M edges, out_channels=1.
#define MAX_N 100000
#define NEG_SLOPE 0.2f

// Scratch (allocation-free rule: __device__ globals)
__device__ float  g_x[MAX_N];      // projected feature x = F @ W  [N] (fp32)
__device__ __half g_xh[MAX_N];     // fp16 copy for the smem gather table
__device__ float2 g_acc[MAX_N];    // per-dst {sum(w*x[src]), sum(w)}; zero-init, self-cleaned

// ---------------------------------------------------------------------------
// Kernel 1: x = F @ W   (warp per row, D=512: 128 float4 per row).
// R2 shape restored — best measured DRAM% (78.1); extra per-warp MLP was neutral.
// ---------------------------------------------------------------------------
__global__ void __launch_bounds__(256) matvec_kernel(
    const float* __restrict__ F, const float* __restrict__ W, int n)
{
    __shared__ float4 sW[128];
    int tid = threadIdx.x;
    if (tid < 128) sW[tid] = reinterpret_cast<const float4*>(W)[tid];
    __syncthreads();

    int warp = tid >> 5;
    int lane = tid & 31;
    int row  = blockIdx.x * 8 + warp;
    if (row >= n) return;

    const float4* Frow = reinterpret_cast<const float4*>(F + (size_t)row * 512);
    float sum = 0.f;
#pragma unroll
    for (int i = 0; i < 4; i++) {
        float4 a = Frow[lane + 32 * i];
        float4 b = sW[lane + 32 * i];
        sum += a.x * b.x + a.y * b.y + a.z * b.z + a.w * b.w;
    }
#pragma unroll
    for (int o = 16; o > 0; o >>= 1)
        sum += __shfl_xor_sync(0xffffffffu, sum, o);

    if (lane == 0) {
        g_x[row]  = sum;
        g_xh[row] = __float2half(sum);
    }
}

// ---------------------------------------------------------------------------
// Kernel 2: persistent fused edge pass.
// x table staged in SMEM as fp16 (200 KB) -> gathers are LDS.
// Softmax max-subtraction dropped (exact ratio invariance; logits are O(1)).
// Explicit red.global.add.v2.f32 guarantees the no-return REDG path
// (ATOMG would pay a 318-cyc return trip + MSHR pressure for nothing).
// ---------------------------------------------------------------------------
__device__ __forceinline__ void process_edge(
    const __half* __restrict__ sx, int s, int d, float as, float ad)
{
    float xs = __half2float(sx[s]);
    float xd = __half2float(sx[d]);
    float l  = fmaf(as, xs, ad * xd);
    l = (l > 0.f) ? l : NEG_SLOPE * l;
    float w = __expf(l);
    float num = w * xs;
    asm volatile("red.global.add.v2.f32 [%0], {%1, %2};"
                 :: "l"(&g_acc[d]), "f"(num), "f"(w) : "memory");
}

__global__ void __launch_bounds__(1024, 1) edge_kernel(
    const int* __restrict__ src, const int* __restrict__ dst,
    int e4, int etail_base, int etail_count, int n,
    const float* __restrict__ att_src, const float* __restrict__ att_dst)
{
    extern __shared__ __half sx[];

    // Stage x table: 100000 halves = 12500 uint4 (16B) vector loads from L2.
    {
        const uint4* xin = reinterpret_cast<const uint4*>(g_xh);
        uint4* xout = reinterpret_cast<uint4*>(sx);
        int nvec = n >> 3;                       // n % 8 == 0 for N=100000
        for (int i = threadIdx.x; i < nvec; i += blockDim.x)
            xout[i] = xin[i];
    }
    __syncthreads();

    const float as = __ldg(att_src);
    const float ad = __ldg(att_dst);

    int gid    = blockIdx.x * blockDim.x + threadIdx.x;
    int stride = gridDim.x * blockDim.x;

    const int4* src4 = reinterpret_cast<const int4*>(src);
    const int4* dst4 = reinterpret_cast<const int4*>(dst);

    for (int i = gid; i < e4; i += stride) {
        int4 s = __ldcs(src4 + i);
        int4 t = __ldcs(dst4 + i);
        process_edge(sx, s.x, t.x, as, ad);
        process_edge(sx, s.y, t.y, as, ad);
        process_edge(sx, s.z, t.z, as, ad);
        process_edge(sx, s.w, t.w, as, ad);
    }
    // scalar tail (E not divisible by 4)
    if (gid < etail_count)
        process_edge(sx, src[etail_base + gid], dst[etail_base + gid], as, ad);
}

// ---------------------------------------------------------------------------
// Kernel 3: fold self-loop analytically, normalize, add bias, and SELF-CLEAN
// g_acc for the next graph replay (device globals are zero-init, so the
// first call is also correct).
// ---------------------------------------------------------------------------
__global__ void finalize_kernel(
    float* __restrict__ out, int n,
    const float* __restrict__ att_src, const float* __restrict__ att_dst,
    const float* __restrict__ bias)
{
    int i = blockIdx.x * blockDim.x + threadIdx.x;
    if (i >= n) return;
    float as = __ldg(att_src);
    float ad = __ldg(att_dst);
    float b  = __ldg(bias);

    float xi = g_x[i];
    float l  = (as + ad) * xi;
    l = (l > 0.f) ? l : NEG_SLOPE * l;
    float w = __expf(l);

    float2 a = g_acc[i];
    out[i] = __fdividef(a.x + w * xi, a.y + w) + b;
    g_acc[i] = make_float2(0.f, 0.f);           // clean for next replay
}

// ---------------------------------------------------------------------------
extern "C" void kernel_launch(void* const* d_in, const int* in_sizes, int n_in,
                              void* d_out, int out_size)
{
    const float* F       = (const float*)d_in[0];
    const int*   ei      = (const int*)  d_in[1];
    const float* W       = (const float*)d_in[2];
    const float* att_src = (const float*)d_in[3];
    const float* att_dst = (const float*)d_in[4];
    const float* bias    = (const float*)d_in[5];
    float*       out     = (float*)d_out;

    const int d = in_sizes[2];        // 512
    const int n = in_sizes[0] / d;    // 100000
    const int E = in_sizes[1] / 2;    // 6400000
    const int* src = ei;
    const int* dst = ei + E;

    const int smem_bytes = n * (int)sizeof(__half);     // 200000 B
    static int configured = 0;        // host-side config memo, not a work guard
    if (!configured) {
        cudaFuncSetAttribute(edge_kernel,
                             cudaFuncAttributeMaxDynamicSharedMemorySize,
                             smem_bytes);
        configured = 1;
    }
    int num_sms = 148;
    cudaDeviceGetAttribute(&num_sms, cudaDevAttrMultiProcessorCount, 0);

    // 1. projection (writes fp32 + fp16 x)
    matvec_kernel<<<(n + 7) / 8, 256>>>(F, W, n);

    // 2. persistent fused edge pass, one 1024-thread block per SM
    int e4 = E / 4;
    int etail_base  = e4 * 4;
    int etail_count = E - etail_base;
    edge_kernel<<<num_sms, 1024, smem_bytes>>>(src, dst, e4, etail_base,
                                               etail_count, n, att_src, att_dst);

    // 3. self-loop fold + normalize + bias + accumulator clean
    finalize_kernel<<<(n + 255) / 256, 256>>>(out, n, att_src, att_dst, bias);
}

// round 6
// speedup vs baseline: 1.0255x; 1.0008x over previous
#include <cuda_runtime.h>
#include <cuda_fp16.h>
#include <cuda_bf16.h>

// Problem constants: N=100000 nodes, D=512, E=6.4M edges, out_channels=1.
#define MAX_N 100000
#define NEG_SLOPE 0.2f

// Scratch (allocation-free rule: __device__ globals)
__device__ float  g_x[MAX_N];      // projected feature x = F @ W  [N] (fp32)
__device__ __half g_xh[MAX_N];     // fp16 copy for the smem gather table
__device__ float2 g_acc[MAX_N];    // per-dst {sum(w*x[src]), sum(w)}; zero-init, self-cleaned

// ---------------------------------------------------------------------------
// Kernel 1: x = F @ W   (warp per row, D=512: 128 float4 per row).
// R2 shape restored — best measured DRAM% (78.1); extra per-warp MLP was neutral.
// ---------------------------------------------------------------------------
__global__ void __launch_bounds__(256) matvec_kernel(
    const float* __restrict__ F, const float* __restrict__ W, int n)
{
    __shared__ float4 sW[128];
    int tid = threadIdx.x;
    if (tid < 128) sW[tid] = reinterpret_cast<const float4*>(W)[tid];
    __syncthreads();

    int warp = tid >> 5;
    int lane = tid & 31;
    int row  = blockIdx.x * 8 + warp;
    if (row >= n) return;

    const float4* Frow = reinterpret_cast<const float4*>(F + (size_t)row * 512);
    float sum = 0.f;
#pragma unroll
    for (int i = 0; i < 4; i++) {
        float4 a = Frow[lane + 32 * i];
        float4 b = sW[lane + 32 * i];
        sum += a.x * b.x + a.y * b.y + a.z * b.z + a.w * b.w;
    }
#pragma unroll
    for (int o = 16; o > 0; o >>= 1)
        sum += __shfl_xor_sync(0xffffffffu, sum, o);

    if (lane == 0) {
        g_x[row]  = sum;
        g_xh[row] = __float2half(sum);
    }
}

// ---------------------------------------------------------------------------
// Kernel 2: persistent fused edge pass.
// x table staged in SMEM as fp16 (200 KB) -> gathers are LDS.
// Softmax max-subtraction dropped (exact ratio invariance; logits are O(1)).
// Explicit red.global.add.v2.f32 guarantees the no-return REDG path
// (ATOMG would pay a 318-cyc return trip + MSHR pressure for nothing).
// ---------------------------------------------------------------------------
__device__ __forceinline__ void process_edge(
    const __half* __restrict__ sx, int s, int d, float as, float ad)
{
    float xs = __half2float(sx[s]);
    float xd = __half2float(sx[d]);
    float l  = fmaf(as, xs, ad * xd);
    l = (l > 0.f) ? l : NEG_SLOPE * l;
    float w = __expf(l);
    float num = w * xs;
    asm volatile("red.global.add.v2.f32 [%0], {%1, %2};"
                 :: "l"(&g_acc[d]), "f"(num), "f"(w) : "memory");
}

__global__ void __launch_bounds__(1024, 1) edge_kernel(
    const int* __restrict__ src, const int* __restrict__ dst,
    int e4, int etail_base, int etail_count, int n,
    const float* __restrict__ att_src, const float* __restrict__ att_dst)
{
    extern __shared__ __half sx[];

    // Stage x table: 100000 halves = 12500 uint4 (16B) vector loads from L2.
    {
        const uint4* xin = reinterpret_cast<const uint4*>(g_xh);
        uint4* xout = reinterpret_cast<uint4*>(sx);
        int nvec = n >> 3;                       // n % 8 == 0 for N=100000
        for (int i = threadIdx.x; i < nvec; i += blockDim.x)
            xout[i] = xin[i];
    }
    __syncthreads();

    const float as = __ldg(att_src);
    const float ad = __ldg(att_dst);

    int gid    = blockIdx.x * blockDim.x + threadIdx.x;
    int stride = gridDim.x * blockDim.x;

    const int4* src4 = reinterpret_cast<const int4*>(src);
    const int4* dst4 = reinterpret_cast<const int4*>(dst);

    for (int i = gid; i < e4; i += stride) {
        int4 s = __ldcs(src4 + i);
        int4 t = __ldcs(dst4 + i);
        process_edge(sx, s.x, t.x, as, ad);
        process_edge(sx, s.y, t.y, as, ad);
        process_edge(sx, s.z, t.z, as, ad);
        process_edge(sx, s.w, t.w, as, ad);
    }
    // scalar tail (E not divisible by 4)
    if (gid < etail_count)
        process_edge(sx, src[etail_base + gid], dst[etail_base + gid], as, ad);
}

// ---------------------------------------------------------------------------
// Kernel 3: fold self-loop analytically, normalize, add bias, and SELF-CLEAN
// g_acc for the next graph replay (device globals are zero-init, so the
// first call is also correct).
// ---------------------------------------------------------------------------
__global__ void finalize_kernel(
    float* __restrict__ out, int n,
    const float* __restrict__ att_src, const float* __restrict__ att_dst,
    const float* __restrict__ bias)
{
    int i = blockIdx.x * blockDim.x + threadIdx.x;
    if (i >= n) return;
    float as = __ldg(att_src);
    float ad = __ldg(att_dst);
    float b  = __ldg(bias);

    float xi = g_x[i];
    float l  = (as + ad) * xi;
    l = (l > 0.f) ? l : NEG_SLOPE * l;
    float w = __expf(l);

    float2 a = g_acc[i];
    out[i] = __fdividef(a.x + w * xi, a.y + w) + b;
    g_acc[i] = make_float2(0.f, 0.f);           // clean for next replay
}

// ---------------------------------------------------------------------------
extern "C" void kernel_launch(void* const* d_in, const int* in_sizes, int n_in,
                              void* d_out, int out_size)
{
    const float* F       = (const float*)d_in[0];
    const int*   ei      = (const int*)  d_in[1];
    const float* W       = (const float*)d_in[2];
    const float* att_src = (const float*)d_in[3];
    const float* att_dst = (const float*)d_in[4];
    const float* bias    = (const float*)d_in[5];
    float*       out     = (float*)d_out;

    const int d = in_sizes[2];        // 512
    const int n = in_sizes[0] / d;    // 100000
    const int E = in_sizes[1] / 2;    // 6400000
    const int* src = ei;
    const int* dst = ei + E;

    const int smem_bytes = n * (int)sizeof(__half);     // 200000 B
    static int configured = 0;        // host-side config memo, not a work guard
    if (!configured) {
        cudaFuncSetAttribute(edge_kernel,
                             cudaFuncAttributeMaxDynamicSharedMemorySize,
                             smem_bytes);
        configured = 1;
    }
    int num_sms = 148;
    cudaDeviceGetAttribute(&num_sms, cudaDevAttrMultiProcessorCount, 0);

    // 1. projection (writes fp32 + fp16 x)
    matvec_kernel<<<(n + 7) / 8, 256>>>(F, W, n);

    // 2. persistent fused edge pass, one 1024-thread block per SM
    int e4 = E / 4;
    int etail_base  = e4 * 4;
    int etail_count = E - etail_base;
    edge_kernel<<<num_sms, 1024, smem_bytes>>>(src, dst, e4, etail_base,
                                               etail_count, n, att_src, att_dst);

    // 3. self-loop fold + normalize + bias + accumulator clean
    finalize_kernel<<<(n + 255) / 256, 256>>>(out, n, att_src, att_dst, bias);
}

// round 7
// speedup vs baseline: 1.0292x; 1.0036x over previous
#include <cuda_runtime.h>
#include <cuda_fp16.h>
#include <cuda_bf16.h>

// Problem constants: N=100000 nodes, D=512, E=6.4M edges, out_channels=1.
#define MAX_N 100000
#define NEG_SLOPE 0.2f

// Scratch (allocation-free rule: __device__ globals)
__device__ float  g_x[MAX_N];            // projected feature x = F @ W (fp32)
__device__ __half g_xh[MAX_N];           // fp16 copy for the smem gather table
__device__ float4 g_acc4[MAX_N / 2];     // per-dst {num,den} pairs, 2/float4; zero-init, self-cleaned

// ---------------------------------------------------------------------------
// Kernel 1: x = F @ W   (warp per row, D=512: 128 float4 per row).
// __ldcs on F: 205 MB one-shot stream -> evict-first, don't churn L2.
// ---------------------------------------------------------------------------
__global__ void __launch_bounds__(256) matvec_kernel(
    const float* __restrict__ F, const float* __restrict__ W, int n)
{
    __shared__ float4 sW[128];
    int tid = threadIdx.x;
    if (tid < 128) sW[tid] = reinterpret_cast<const float4*>(W)[tid];
    __syncthreads();

    int warp = tid >> 5;
    int lane = tid & 31;
    int row  = blockIdx.x * 8 + warp;
    if (row >= n) return;

    const float4* Frow = reinterpret_cast<const float4*>(F + (size_t)row * 512);
    float sum = 0.f;
#pragma unroll
    for (int i = 0; i < 4; i++) {
        float4 a = __ldcs(Frow + lane + 32 * i);
        float4 b = sW[lane + 32 * i];
        sum += a.x * b.x + a.y * b.y + a.z * b.z + a.w * b.w;
    }
#pragma unroll
    for (int o = 16; o > 0; o >>= 1)
        sum += __shfl_xor_sync(0xffffffffu, sum, o);

    if (lane == 0) {
        g_x[row]  = sum;
        g_xh[row] = __float2half(sum);
    }
}

// ---------------------------------------------------------------------------
// Kernel 2: persistent fused edge pass (UNCHANGED — at its REDG issue floor).
// x table staged in SMEM as fp16 (200 KB) -> gathers are LDS.
// Softmax max-subtraction dropped (exact ratio invariance; logits are O(1)).
// ---------------------------------------------------------------------------
__device__ __forceinline__ void process_edge(
    const __half* __restrict__ sx, int s, int d, float as, float ad)
{
    float xs = __half2float(sx[s]);
    float xd = __half2float(sx[d]);
    float l  = fmaf(as, xs, ad * xd);
    l = (l > 0.f) ? l : NEG_SLOPE * l;
    float w = __expf(l);
    float num = w * xs;
    float2* acc = reinterpret_cast<float2*>(g_acc4) + d;
    asm volatile("red.global.add.v2.f32 [%0], {%1, %2};"
                 :: "l"(acc), "f"(num), "f"(w) : "memory");
}

__global__ void __launch_bounds__(1024, 1) edge_kernel(
    const int* __restrict__ src, const int* __restrict__ dst,
    int e4, int etail_base, int etail_count, int n,
    const float* __restrict__ att_src, const float* __restrict__ att_dst)
{
    extern __shared__ __half sx[];

    // Stage x table: 100000 halves = 12500 uint4 (16B) vector loads from L2.
    {
        const uint4* xin = reinterpret_cast<const uint4*>(g_xh);
        uint4* xout = reinterpret_cast<uint4*>(sx);
        int nvec = n >> 3;                       // n % 8 == 0 for N=100000
        for (int i = threadIdx.x; i < nvec; i += blockDim.x)
            xout[i] = xin[i];
    }
    __syncthreads();

    const float as = __ldg(att_src);
    const float ad = __ldg(att_dst);

    int gid    = blockIdx.x * blockDim.x + threadIdx.x;
    int stride = gridDim.x * blockDim.x;

    const int4* src4 = reinterpret_cast<const int4*>(src);
    const int4* dst4 = reinterpret_cast<const int4*>(dst);

    for (int i = gid; i < e4; i += stride) {
        int4 s = __ldcs(src4 + i);
        int4 t = __ldcs(dst4 + i);
        process_edge(sx, s.x, t.x, as, ad);
        process_edge(sx, s.y, t.y, as, ad);
        process_edge(sx, s.z, t.z, as, ad);
        process_edge(sx, s.w, t.w, as, ad);
    }
    // scalar tail (E not divisible by 4)
    if (gid < etail_count)
        process_edge(sx, src[etail_base + gid], dst[etail_base + gid], as, ad);
}

// ---------------------------------------------------------------------------
// Kernel 3: fold self-loop, normalize, bias, and SELF-CLEAN g_acc for the
// next replay. Vectorized: 2 nodes/thread (float4 acc load, float2 x/out).
// ---------------------------------------------------------------------------
__global__ void __launch_bounds__(256) finalize_kernel(
    float* __restrict__ out, int n2,
    const float* __restrict__ att_src, const float* __restrict__ att_dst,
    const float* __restrict__ bias)
{
    int i = blockIdx.x * blockDim.x + threadIdx.x;   // pair index
    if (i >= n2) return;
    float as = __ldg(att_src);
    float ad = __ldg(att_dst);
    float b  = __ldg(bias);
    float aa = as + ad;

    float2 xi = reinterpret_cast<const float2*>(g_x)[i];
    float4 a  = g_acc4[i];

    float l0 = aa * xi.x; l0 = (l0 > 0.f) ? l0 : NEG_SLOPE * l0;
    float l1 = aa * xi.y; l1 = (l1 > 0.f) ? l1 : NEG_SLOPE * l1;
    float w0 = __expf(l0);
    float w1 = __expf(l1);

    float2 o;
    o.x = __fdividef(a.x + w0 * xi.x, a.y + w0) + b;
    o.y = __fdividef(a.z + w1 * xi.y, a.w + w1) + b;
    reinterpret_cast<float2*>(out)[i] = o;

    g_acc4[i] = make_float4(0.f, 0.f, 0.f, 0.f);    // clean for next replay
}

// ---------------------------------------------------------------------------
extern "C" void kernel_launch(void* const* d_in, const int* in_sizes, int n_in,
                              void* d_out, int out_size)
{
    const float* F       = (const float*)d_in[0];
    const int*   ei      = (const int*)  d_in[1];
    const float* W       = (const float*)d_in[2];
    const float* att_src = (const float*)d_in[3];
    const float* att_dst = (const float*)d_in[4];
    const float* bias    = (const float*)d_in[5];
    float*       out     = (float*)d_out;

    const int d = in_sizes[2];        // 512
    const int n = in_sizes[0] / d;    // 100000 (even)
    const int E = in_sizes[1] / 2;    // 6400000
    const int* src = ei;
    const int* dst = ei + E;

    const int smem_bytes = n * (int)sizeof(__half);     // 200000 B
    static int configured = 0;        // host-side config memo, not a work guard
    if (!configured) {
        cudaFuncSetAttribute(edge_kernel,
                             cudaFuncAttributeMaxDynamicSharedMemorySize,
                             smem_bytes);
        configured = 1;
    }
    int num_sms = 148;
    cudaDeviceGetAttribute(&num_sms, cudaDevAttrMultiProcessorCount, 0);

    // 1. projection (writes fp32 + fp16 x)
    matvec_kernel<<<(n + 7) / 8, 256>>>(F, W, n);

    // 2. persistent fused edge pass, one 1024-thread block per SM
    int e4 = E / 4;
    int etail_base  = e4 * 4;
    int etail_count = E - etail_base;
    edge_kernel<<<num_sms, 1024, smem_bytes>>>(src, dst, e4, etail_base,
                                               etail_count, n, att_src, att_dst);

    // 3. self-loop fold + normalize + bias + accumulator clean (2 nodes/thread)
    int n2 = n / 2;
    finalize_kernel<<<(n2 + 255) / 256, 256>>>(out, n2, att_src, att_dst, bias);
}

// round 8
// speedup vs baseline: 1.0308x; 1.0016x over previous
#include <cuda_runtime.h>
#include <cuda_fp16.h>
#include <cuda_bf16.h>

// Problem constants: N=100000 nodes, D=512, E=6.4M edges, out_channels=1.
#define MAX_N 100000
#define NEG_SLOPE 0.2f
#define LOG2E 1.4426950408889634f

// Scratch (allocation-free rule: __device__ globals)
__device__ float  g_x[MAX_N];            // projected feature x = F @ W (fp32)
__device__ __half g_xh[MAX_N];           // fp16 copy for the smem gather table
__device__ float4 g_acc4[MAX_N / 2];     // per-dst {num,den} pairs; zero-init, self-cleaned

// ---------------------------------------------------------------------------
// Kernel 1: x = F @ W   (warp per row, D=512: 128 float4 per row).
// At the HBM plateau (78% of spec) — do not touch.
// ---------------------------------------------------------------------------
__global__ void __launch_bounds__(256) matvec_kernel(
    const float* __restrict__ F, const float* __restrict__ W, int n)
{
    __shared__ float4 sW[128];
    int tid = threadIdx.x;
    if (tid < 128) sW[tid] = reinterpret_cast<const float4*>(W)[tid];
    __syncthreads();

    int warp = tid >> 5;
    int lane = tid & 31;
    int row  = blockIdx.x * 8 + warp;
    if (row >= n) return;

    const float4* Frow = reinterpret_cast<const float4*>(F + (size_t)row * 512);
    float sum = 0.f;
#pragma unroll
    for (int i = 0; i < 4; i++) {
        float4 a = __ldcs(Frow + lane + 32 * i);
        float4 b = sW[lane + 32 * i];
        sum += a.x * b.x + a.y * b.y + a.z * b.z + a.w * b.w;
    }
#pragma unroll
    for (int o = 16; o > 0; o >>= 1)
        sum += __shfl_xor_sync(0xffffffffu, sum, o);

    if (lane == 0) {
        g_x[row]  = sum;
        g_xh[row] = __float2half(sum);
    }
}

// ---------------------------------------------------------------------------
// Kernel 2: persistent fused edge pass (REDG issue floor).
// x table staged in SMEM as fp16 (200 KB) -> gathers are LDS.
// Softmax max-subtraction dropped (exact ratio invariance; logits are O(1)).
// log2e pre-folded into as/ad: per-edge exp is a single EX2 on
// max(l, 0.2*l)  (leaky_relu(l) == max(l, 0.2l) identically for slope<1).
// ---------------------------------------------------------------------------
__device__ __forceinline__ void process_edge(
    const __half* __restrict__ sx, int s, int d, float as2, float ad2)
{
    float xs = __half2float(sx[s]);
    float xd = __half2float(sx[d]);
    float l  = fmaf(as2, xs, ad2 * xd);        // already scaled by log2e
    float t  = fmaxf(l, NEG_SLOPE * l);        // leaky_relu == max(l, 0.2l)
    float w  = exp2f(t);
    float num = w * xs;
    float2* acc = reinterpret_cast<float2*>(g_acc4) + d;
    asm volatile("red.global.add.v2.f32 [%0], {%1, %2};"
                 :: "l"(acc), "f"(num), "f"(w) : "memory");
}

__global__ void __launch_bounds__(1024, 1) edge_kernel(
    const int* __restrict__ src, const int* __restrict__ dst,
    int e4, int etail_base, int etail_count, int n,
    const float* __restrict__ att_src, const float* __restrict__ att_dst)
{
    extern __shared__ __half sx[];

    // Stage x table: 100000 halves = 12500 uint4 (16B) vector loads from L2.
    {
        const uint4* xin = reinterpret_cast<const uint4*>(g_xh);
        uint4* xout = reinterpret_cast<uint4*>(sx);
        int nvec = n >> 3;                       // n % 8 == 0 for N=100000
        for (int i = threadIdx.x; i < nvec; i += blockDim.x)
            xout[i] = xin[i];
    }
    __syncthreads();

    const float as2 = __ldg(att_src) * LOG2E;
    const float ad2 = __ldg(att_dst) * LOG2E;

    int gid    = blockIdx.x * blockDim.x + threadIdx.x;
    int stride = gridDim.x * blockDim.x;

    const int4* src4 = reinterpret_cast<const int4*>(src);
    const int4* dst4 = reinterpret_cast<const int4*>(dst);

    for (int i = gid; i < e4; i += stride) {
        int4 s = __ldcs(src4 + i);
        int4 t = __ldcs(dst4 + i);
        process_edge(sx, s.x, t.x, as2, ad2);
        process_edge(sx, s.y, t.y, as2, ad2);
        process_edge(sx, s.z, t.z, as2, ad2);
        process_edge(sx, s.w, t.w, as2, ad2);
    }
    // scalar tail (E not divisible by 4)
    if (gid < etail_count)
        process_edge(sx, src[etail_base + gid], dst[etail_base + gid], as2, ad2);
}

// ---------------------------------------------------------------------------
// Kernel 3: fold self-loop, normalize, bias; SELF-CLEAN g_acc for next replay.
// 4 nodes/thread, 128-thread blocks -> 196 blocks (single wave), 4
// independent chains per thread for latency hiding.
// ---------------------------------------------------------------------------
__global__ void __launch_bounds__(128) finalize_kernel(
    float* __restrict__ out, int n4,
    const float* __restrict__ att_src, const float* __restrict__ att_dst,
    const float* __restrict__ bias)
{
    int i = blockIdx.x * blockDim.x + threadIdx.x;   // quad index
    if (i >= n4) return;
    float aa = (__ldg(att_src) + __ldg(att_dst)) * LOG2E;
    float b  = __ldg(bias);

    float4 xi = reinterpret_cast<const float4*>(g_x)[i];
    float4 a0 = g_acc4[2 * i];
    float4 a1 = g_acc4[2 * i + 1];

    float w0 = exp2f(fmaxf(aa * xi.x, NEG_SLOPE * (aa * xi.x)));
    float w1 = exp2f(fmaxf(aa * xi.y, NEG_SLOPE * (aa * xi.y)));
    float w2 = exp2f(fmaxf(aa * xi.z, NEG_SLOPE * (aa * xi.z)));
    float w3 = exp2f(fmaxf(aa * xi.w, NEG_SLOPE * (aa * xi.w)));

    float4 o;
    o.x = __fdividef(a0.x + w0 * xi.x, a0.y + w0) + b;
    o.y = __fdividef(a0.z + w1 * xi.y, a0.w + w1) + b;
    o.z = __fdividef(a1.x + w2 * xi.z, a1.y + w2) + b;
    o.w = __fdividef(a1.z + w3 * xi.w, a1.w + w3) + b;
    reinterpret_cast<float4*>(out)[i] = o;

    g_acc4[2 * i]     = make_float4(0.f, 0.f, 0.f, 0.f);  // clean for next replay
    g_acc4[2 * i + 1] = make_float4(0.f, 0.f, 0.f, 0.f);
}

// ---------------------------------------------------------------------------
extern "C" void kernel_launch(void* const* d_in, const int* in_sizes, int n_in,
                              void* d_out, int out_size)
{
    const float* F       = (const float*)d_in[0];
    const int*   ei      = (const int*)  d_in[1];
    const float* W       = (const float*)d_in[2];
    const float* att_src = (const float*)d_in[3];
    const float* att_dst = (const float*)d_in[4];
    const float* bias    = (const float*)d_in[5];
    float*       out     = (float*)d_out;

    const int d = in_sizes[2];        // 512
    const int n = in_sizes[0] / d;    // 100000 (divisible by 4)
    const int E = in_sizes[1] / 2;    // 6400000
    const int* src = ei;
    const int* dst = ei + E;

    const int smem_bytes = n * (int)sizeof(__half);     // 200000 B
    static int configured = 0;        // host-side config memo, not a work guard
    if (!configured) {
        cudaFuncSetAttribute(edge_kernel,
                             cudaFuncAttributeMaxDynamicSharedMemorySize,
                             smem_bytes);
        configured = 1;
    }
    int num_sms = 148;
    cudaDeviceGetAttribute(&num_sms, cudaDevAttrMultiProcessorCount, 0);

    // 1. projection (writes fp32 + fp16 x)
    matvec_kernel<<<(n + 7) / 8, 256>>>(F, W, n);

    // 2. persistent fused edge pass, one 1024-thread block per SM
    int e4 = E / 4;
    int etail_base  = e4 * 4;
    int etail_count = E - etail_base;
    edge_kernel<<<num_sms, 1024, smem_bytes>>>(src, dst, e4, etail_base,
                                               etail_count, n, att_src, att_dst);

    // 3. self-loop fold + normalize + bias + accumulator clean (4 nodes/thread)
    int n4 = n / 4;
    finalize_kernel<<<(n4 + 127) / 128, 128>>>(out, n4, att_src, att_dst, bias);
}